// round 3
// baseline (speedup 1.0000x reference)
#include <cuda_runtime.h>
#include <math.h>
#include <stdint.h>

// Problem constants (fixed by the seeded reference):
//   m=8, nc=1024, nt=512, dim=2, PPU=64 -> grid 129x129 per batch.
#define M_B   8
#define NC    1024
#define NT    512
#define AX    129
#define NG    (AX * AX)            // 16641
#define HALF  64
#define INV_PPU (1.0f / 64.0f)
#define X_TOTAL (M_B * NG * 2)     // x_grid floats, then z_grid

#define KC    64                   // contexts per chunk
#define NCHK  16                   // 1024 / 64
#define JTW   8                    // j columns per CTA
#define NJT   17                   // ceil(129/8)
#define NTHR  384                  // 8 consumer warps + 4 producer warps

// Shared memory layout (dynamic)
#define WXD_STRIDE 1056                       // 132 i-slots * 8B ({w,w} duplicated)
#define WXD_BUF   (KC * WXD_STRIDE)           // 67584
#define WYY_BUF   (KC * 96)                   // 6144: per c: 2 jg * 48B (2jp x 3ch u64)
#define OFF_WXD   0
#define OFF_WYY   (2 * WXD_BUF)               // 135168
#define OFF_SXY   (OFF_WYY + 2 * WYY_BUF)     // 147456: KC float4 {vx*k0, vy*k1, y0, y1}
#define OFF_GXK   (OFF_SXY + KC * 16)         // 148480: 132 floats gx*k0
#define OFF_GYK   (OFF_GXK + 132 * 4)         // 149008: 8 floats gy*k1
#define OFF_RED   (OFF_GYK + 32)              // 149040: reduction scratch 48 floats
#define OFF_MID   (OFF_RED + 192)             // 149232: mid.x, mid.y
#define SMEM_TOTAL (OFF_MID + 64)             // 149296

__device__ __forceinline__ float ex2f(float x) {
    float r; asm("ex2.approx.f32 %0, %1;" : "=f"(r) : "f"(x)); return r;
}
__device__ __forceinline__ float soft_k(float p) {
    // weight = 2^(-((dx*k)^2)) with k = sqrt(0.5*log2(e)) / (1e-5 + softplus(p))
    float ls = 1e-5f + log1pf(expf(p));
    return sqrtf(0.5f * 1.44269504088896341f) / ls;
}
__device__ __forceinline__ uint32_t sm32(const void* p) {
    uint32_t a;
    asm("{ .reg .u64 t; cvta.to.shared.u64 t, %1; cvt.u32.u64 %0, t; }" : "=r"(a) : "l"(p));
    return a;
}
#define FMA2(acc, a, b) \
    asm("fma.rn.f32x2 %0, %1, %2, %0;" : "+l"(acc) : "l"(a), "l"(b))

// Produce one K-chunk of factor tables into buffer (ch & 1).
__device__ __forceinline__ void produce_chunk(char* sm, uint32_t smb, int ch,
                                              int tl, int nthr, bool allbar,
                                              int b, int jt, float k0, float k1,
                                              const float* __restrict__ xc,
                                              const float* __restrict__ yc) {
    const int c0 = ch * KC;
    float4* sxy = (float4*)(sm + OFF_SXY);
    if (tl < KC) {
        const float2 vx = *(const float2*)(xc + (size_t)(b * NC + c0 + tl) * 2);
        const float2 vy = *(const float2*)(yc + (size_t)(b * NC + c0 + tl) * 2);
        sxy[tl] = make_float4(vx.x * k0, vx.y * k1, vy.x, vy.y);
    }
    if (allbar) __syncthreads();
    else        asm volatile("bar.sync 1, 128;" ::: "memory");

    const int buf = ch & 1;
    const float* gxk = (const float*)(sm + OFF_GXK);
    const uint32_t wxb = smb + OFF_WXD + buf * WXD_BUF;
    for (int idx = tl; idx < KC * AX; idx += nthr) {
        const int c = idx / AX;
        const int i = idx - c * AX;
        const float d = gxk[i] - sxy[c].x;
        const float w = ex2f(-(d * d));
        asm volatile("st.shared.v2.f32 [%0], {%1, %1};"
                     :: "r"(wxb + (uint32_t)c * WXD_STRIDE + (uint32_t)i * 8), "f"(w) : "memory");
    }
    const float* gyk = (const float*)(sm + OFF_GYK);
    const uint32_t wyb = smb + OFF_WYY + buf * WYY_BUF;
    for (int idx = tl; idx < KC * JTW; idx += nthr) {
        const int c = idx >> 3;
        const int jl = idx & 7;
        const int jglob = jt * JTW + jl;
        const float4 v = sxy[c];
        const float d = gyk[jl] - v.y;
        float w = ex2f(-(d * d));
        if (jglob > 128) w = 0.0f;
        const uint32_t a = wyb + (uint32_t)c * 96
                         + (uint32_t)((jl >> 2) * 48 + ((jl >> 1) & 1) * 24 + (jl & 1) * 4);
        asm volatile("st.shared.f32 [%0], %1;" :: "r"(a),      "f"(w * v.z) : "memory");
        asm volatile("st.shared.f32 [%0], %1;" :: "r"(a + 8),  "f"(w * v.w) : "memory");
        asm volatile("st.shared.f32 [%0], %1;" :: "r"(a + 16), "f"(w)       : "memory");
    }
}

extern __shared__ char dynsm[];

__global__ void __launch_bounds__(NTHR, 1)
fused_kernel(const float* __restrict__ xc, const float* __restrict__ yc,
             const float* __restrict__ xt, const float* __restrict__ lsp,
             float* __restrict__ out) {
    char* sm = dynsm;
    const uint32_t smb = sm32(sm);
    const int tid = threadIdx.x;
    const int b = blockIdx.y;
    const int jt = blockIdx.x;
    const int w = tid >> 5, lane = tid & 31;

    // ---- per-CTA min/max over concat(xc, xt) for batch b ----
    float mn0 = 1e30f, mx0 = -1e30f, mn1 = 1e30f, mx1 = -1e30f;
    for (int idx = tid; idx < NC + NT; idx += NTHR) {
        const float2 p = (idx < NC)
            ? *(const float2*)(xc + (size_t)(b * NC + idx) * 2)
            : *(const float2*)(xt + (size_t)(b * NT + idx - NC) * 2);
        mn0 = fminf(mn0, p.x); mx0 = fmaxf(mx0, p.x);
        mn1 = fminf(mn1, p.y); mx1 = fmaxf(mx1, p.y);
    }
    for (int o = 16; o; o >>= 1) {
        mn0 = fminf(mn0, __shfl_xor_sync(~0u, mn0, o));
        mx0 = fmaxf(mx0, __shfl_xor_sync(~0u, mx0, o));
        mn1 = fminf(mn1, __shfl_xor_sync(~0u, mn1, o));
        mx1 = fmaxf(mx1, __shfl_xor_sync(~0u, mx1, o));
    }
    float* sred = (float*)(sm + OFF_RED);
    float* smid = (float*)(sm + OFF_MID);
    if (lane == 0) { sred[w] = mn0; sred[12 + w] = mx0; sred[24 + w] = mn1; sred[36 + w] = mx1; }
    __syncthreads();
    if (tid == 0) {
        float a = sred[0], bb = sred[12], c = sred[24], d = sred[36];
        #pragma unroll
        for (int k = 1; k < 12; k++) {
            a = fminf(a, sred[k]);      bb = fmaxf(bb, sred[12 + k]);
            c = fminf(c, sred[24 + k]); d  = fmaxf(d,  sred[36 + k]);
        }
        smid[0] = 0.5f * (a + bb); smid[1] = 0.5f * (c + d);
    }
    const float k0 = soft_k(lsp[0]);
    const float k1 = soft_k(lsp[1]);
    __syncthreads();
    const float midx = smid[0], midy = smid[1];
    float* gxk = (float*)(sm + OFF_GXK);
    float* gyk = (float*)(sm + OFF_GYK);
    if (tid < 132) gxk[tid] = (midx + (float)(tid - HALF) * INV_PPU) * k0;
    if (tid < 8)   gyk[tid] = (midy + (float)(jt * JTW + tid - HALF) * INV_PPU) * k1;
    __syncthreads();

    // ---- prefill chunk 0 with all threads ----
    produce_chunk(sm, smb, 0, tid, NTHR, true, b, jt, k0, k1, xc, yc);
    __syncthreads();

    // consumer identity: warps 0..7 = (ig 0..3) x (jg 0..1); i = ig*32 + lane
    int ti = 0, tjg = 0;
    if (tid < 256) { ti = (w & 3) * 32 + lane; tjg = w >> 2; }
    // edge identity: producer warps 8..11, lanes 0..5 -> 24 items (8 j x 3 ch)
    int ej = 0, ech = 0; bool edge_active = false;
    if (tid >= 256 && lane < 6) {
        const int item = (w - 8) * 6 + lane;
        ej = item / 3; ech = item - ej * 3;
        edge_active = true;
    }
    const uint32_t eya_off = (uint32_t)((ej >> 2) * 48 + ((ej >> 1) & 1) * 24 + ech * 8 + (ej & 1) * 4);

    unsigned long long a0 = 0, a1 = 0, a2 = 0, a3 = 0, a4 = 0, a5 = 0;
    float eacc = 0.0f;

    for (int ch = 0; ch < NCHK; ch++) {
        const int buf = ch & 1;
        if (tid < 256) {
            uint32_t wxa = smb + OFF_WXD + buf * WXD_BUF + (uint32_t)ti * 8;
            uint32_t wya = smb + OFF_WYY + buf * WYY_BUF + (uint32_t)tjg * 48;
            #pragma unroll 4
            for (int kk = 0; kk < KC; kk++) {
                unsigned long long wx, y0, y1, y2, y3, y4, y5;
                asm("ld.shared.u64 %0, [%1];" : "=l"(wx) : "r"(wxa));
                asm("ld.shared.v2.u64 {%0,%1}, [%2];" : "=l"(y0), "=l"(y1) : "r"(wya));
                asm("ld.shared.v2.u64 {%0,%1}, [%2];" : "=l"(y2), "=l"(y3) : "r"(wya + 16));
                asm("ld.shared.v2.u64 {%0,%1}, [%2];" : "=l"(y4), "=l"(y5) : "r"(wya + 32));
                FMA2(a0, wx, y0); FMA2(a1, wx, y1); FMA2(a2, wx, y2);
                FMA2(a3, wx, y3); FMA2(a4, wx, y4); FMA2(a5, wx, y5);
                wxa += WXD_STRIDE; wya += 96;
            }
        } else {
            if (ch + 1 < NCHK)
                produce_chunk(sm, smb, ch + 1, tid - 256, 128, false, b, jt, k0, k1, xc, yc);
            if (edge_active) {
                uint32_t wxa = smb + OFF_WXD + buf * WXD_BUF + 128u * 8;
                uint32_t wya = smb + OFF_WYY + buf * WYY_BUF + eya_off;
                #pragma unroll 4
                for (int kk = 0; kk < KC; kk++) {
                    float wv, yv;
                    asm("ld.shared.f32 %0, [%1];" : "=f"(wv) : "r"(wxa));
                    asm("ld.shared.f32 %0, [%1];" : "=f"(yv) : "r"(wya));
                    eacc = fmaf(wv, yv, eacc);
                    wxa += WXD_STRIDE; wya += 96;
                }
            }
        }
        __syncthreads();
    }

    // ---- stores ----
    const int j0base = jt * JTW;
    if (tid < 256) {
        const int i = ti;
        const int j0 = j0base + tjg * 4;
        const float gx = midx + (float)(i - HALF) * INV_PPU;
        union { unsigned long long u; float f[2]; } v;
        unsigned long long accs[6] = { a0, a1, a2, a3, a4, a5 };
        #pragma unroll
        for (int jp = 0; jp < 2; jp++) {
            #pragma unroll
            for (int chn = 0; chn < 3; chn++) {
                v.u = accs[jp * 3 + chn];
                #pragma unroll
                for (int e = 0; e < 2; e++) {
                    const int j = j0 + jp * 2 + e;
                    if (j < AX)
                        out[(size_t)X_TOTAL + ((size_t)(b * NG) + (size_t)i * AX + j) * 3 + chn] = v.f[e];
                }
            }
        }
        #pragma unroll
        for (int jj = 0; jj < 4; jj++) {
            const int j = j0 + jj;
            if (j < AX) {
                const float gy = midy + (float)(j - HALF) * INV_PPU;
                float* xg = out + ((size_t)(b * NG) + (size_t)i * AX + j) * 2;
                xg[0] = gx; xg[1] = gy;
            }
        }
    } else if (edge_active) {
        const int j = j0base + ej;
        if (j < AX) {
            out[(size_t)X_TOTAL + ((size_t)(b * NG) + (size_t)128 * AX + j) * 3 + ech] = eacc;
            if (ech == 0) {
                const float gx = midx + (float)(128 - HALF) * INV_PPU;
                const float gy = midy + (float)(j - HALF) * INV_PPU;
                float* xg = out + ((size_t)(b * NG) + (size_t)128 * AX + j) * 2;
                xg[0] = gx; xg[1] = gy;
            }
        }
    }
}

extern "C" void kernel_launch(void* const* d_in, const int* in_sizes, int n_in,
                              void* d_out, int out_size) {
    const float* xc  = (const float*)d_in[0];
    const float* yc  = (const float*)d_in[1];
    const float* xt  = (const float*)d_in[2];
    const float* lsp = (const float*)d_in[3];
    float* out = (float*)d_out;

    cudaFuncSetAttribute(fused_kernel, cudaFuncAttributeMaxDynamicSharedMemorySize, SMEM_TOTAL);
    dim3 grid(NJT, M_B);
    fused_kernel<<<grid, NTHR, SMEM_TOTAL>>>(xc, yc, xt, lsp, out);
}